// round 1
// baseline (speedup 1.0000x reference)
#include <cuda_runtime.h>
#include <math.h>

// Problem constants
#define SEQ     2048
#define BATCH   2
#define HIDDEN  1024
#define NHEAD   16
#define HDIM    64
#define NH      (BATCH * NHEAD)   // 32 head-instances
#define TOK     (SEQ * BATCH)     // 4096 tokens

// Scratch: Q,K stored d-major [n][d][s] (so attention loads transposed tiles
// directly, conflict-free smem stores). V stored natural [n][s][d].
__device__ float g_q[(size_t)NH * HDIM * SEQ];
__device__ float g_k[(size_t)NH * HDIM * SEQ];
__device__ float g_v[(size_t)NH * SEQ * HDIM];

// ---------------------------------------------------------------------------
// Kernel 1: fused QKV projection.  C[t][c] = sum_k A[t][k] * W[k][c] + bias[c]
// A = hidden_states flattened [4096][1024] (row = s*B+b).
// Tile: BM=128, BN=128, BK=16. 256 threads, 8x8 micro-tile per thread.
// blockIdx.z selects {Q,K,V}; Q,K written d-major, V written s-major.
// ---------------------------------------------------------------------------
__global__ __launch_bounds__(256) void qkv_kernel(
    const float* __restrict__ A,
    const float* __restrict__ Wq, const float* __restrict__ bq,
    const float* __restrict__ Wk, const float* __restrict__ bk,
    const float* __restrict__ Wv, const float* __restrict__ bv)
{
    const int z = blockIdx.z;
    const float* W    = (z == 0) ? Wq : (z == 1) ? Wk : Wv;
    const float* bias = (z == 0) ? bq : (z == 1) ? bk : bv;
    float* outp       = (z == 0) ? g_q : (z == 1) ? g_k : g_v;

    __shared__ float As[16 * 132];  // A tile transposed: As[kk][r], stride 132
    __shared__ float Bs[16 * 128];  // W tile natural:   Bs[kk][c]

    const int tid = threadIdx.x;
    const int ty = tid >> 4;        // 0..15
    const int tx = tid & 15;        // 0..15
    const int t0 = blockIdx.y * 128;
    const int c0 = blockIdx.x * 128;

    float acc[8][8];
#pragma unroll
    for (int i = 0; i < 8; i++)
#pragma unroll
        for (int j = 0; j < 8; j++) acc[i][j] = 0.f;

    for (int k0 = 0; k0 < HIDDEN; k0 += 16) {
        // Load A tile 128x16, store transposed.
#pragma unroll
        for (int i = 0; i < 2; i++) {
            int idx = tid + i * 256;          // 0..511 float4s
            int r   = idx >> 2;               // 0..127
            int kk4 = (idx & 3) * 4;
            float4 a = *(const float4*)(A + (size_t)(t0 + r) * HIDDEN + k0 + kk4);
            As[(kk4 + 0) * 132 + r] = a.x;
            As[(kk4 + 1) * 132 + r] = a.y;
            As[(kk4 + 2) * 132 + r] = a.z;
            As[(kk4 + 3) * 132 + r] = a.w;
        }
        // Load W tile 16x128, natural layout.
#pragma unroll
        for (int i = 0; i < 2; i++) {
            int idx = tid + i * 256;
            int kk  = idx >> 5;               // 0..15
            int c4  = (idx & 31) * 4;
            *(float4*)(Bs + kk * 128 + c4) =
                *(const float4*)(W + (size_t)(k0 + kk) * HIDDEN + c0 + c4);
        }
        __syncthreads();

#pragma unroll
        for (int kk = 0; kk < 16; kk++) {
            float4 a0 = *(const float4*)(As + kk * 132 + ty * 8);
            float4 a1 = *(const float4*)(As + kk * 132 + ty * 8 + 4);
            float4 b0 = *(const float4*)(Bs + kk * 128 + tx * 8);
            float4 b1 = *(const float4*)(Bs + kk * 128 + tx * 8 + 4);
            float av[8] = {a0.x, a0.y, a0.z, a0.w, a1.x, a1.y, a1.z, a1.w};
            float bw[8] = {b0.x, b0.y, b0.z, b0.w, b1.x, b1.y, b1.z, b1.w};
#pragma unroll
            for (int mi = 0; mi < 8; mi++)
#pragma unroll
                for (int ni = 0; ni < 8; ni++)
                    acc[mi][ni] += av[mi] * bw[ni];
        }
        __syncthreads();
    }

    // Epilogue: head-layout scatter.
#pragma unroll
    for (int mi = 0; mi < 8; mi++) {
        int t = t0 + ty * 8 + mi;
        int s = t >> 1;        // / BATCH
        int b = t & 1;
#pragma unroll
        for (int ni = 0; ni < 8; ni++) {
            int c = c0 + tx * 8 + ni;
            int h = c >> 6;
            int d = c & 63;
            int n = b * NHEAD + h;
            float val = acc[mi][ni] + bias[c];
            if (z <= 1) {
                // d-major: [n][d][s]
                outp[((size_t)n * HDIM + d) * SEQ + s] = val;
            } else {
                // s-major: [n][s][d]
                outp[((size_t)n * SEQ + s) * HDIM + d] = val;
            }
        }
    }
}

// ---------------------------------------------------------------------------
// Kernel 2: flash attention, fp32. One block = one head-instance x 64 queries.
// 256 threads (16x16), 4x4 micro-tiles. Online softmax with register stats.
// smem: Qt[d][q] (64x68), Kt[d][k] (64x68), Pt[k][q] (64x68), Vs[k][d] (64x64)
// ---------------------------------------------------------------------------
#define ATTN_SMEM ((3 * 64 * 68 + 64 * 64) * 4)

__global__ __launch_bounds__(256) void attn_kernel(
    const float* __restrict__ mask, float* __restrict__ out)
{
    extern __shared__ float sm[];
    float* Qt = sm;                 // [64][68]
    float* Kt = Qt + 64 * 68;       // [64][68]
    float* Pt = Kt + 64 * 68;       // [64][68]
    float* Vs = Pt + 64 * 68;       // [64][64]

    const int n  = blockIdx.x;        // head-instance 0..31  (n = b*16 + h)
    const int q0 = blockIdx.y * 64;
    const int b  = n >> 4;
    const int h  = n & 15;
    const int tid = threadIdx.x;
    const int ty = tid >> 4;
    const int tx = tid & 15;

    const float* qg = g_q + (size_t)n * HDIM * SEQ;   // [d][s]
    const float* kg = g_k + (size_t)n * HDIM * SEQ;   // [d][s]
    const float* vg = g_v + (size_t)n * SEQ * HDIM;   // [s][d]

    // Load Q tile: Qt[d][q_local]
#pragma unroll
    for (int i = 0; i < 4; i++) {
        int idx = tid + i * 256;       // 0..1023 float4s
        int d   = idx >> 4;            // 0..63
        int s4  = (idx & 15) * 4;
        *(float4*)(Qt + d * 68 + s4) =
            *(const float4*)(qg + (size_t)d * SEQ + q0 + s4);
    }

    float o[4][4];
    float m_r[4], l_r[4];
#pragma unroll
    for (int i = 0; i < 4; i++) {
        m_r[i] = -1e30f;
        l_r[i] = 0.f;
#pragma unroll
        for (int j = 0; j < 4; j++) o[i][j] = 0.f;
    }

    const float scale = 0.125f;  // 1/sqrt(64)

    for (int kt = 0; kt < SEQ; kt += 64) {
        __syncthreads();  // previous PV done (and Qt ready on first iter)

        // Load K tile (already d-major in global): Kt[d][k_local]
#pragma unroll
        for (int i = 0; i < 4; i++) {
            int idx = tid + i * 256;
            int d   = idx >> 4;
            int s4  = (idx & 15) * 4;
            *(float4*)(Kt + d * 68 + s4) =
                *(const float4*)(kg + (size_t)d * SEQ + kt + s4);
        }
        // Load V tile natural: Vs[k_local][d]
#pragma unroll
        for (int i = 0; i < 4; i++) {
            int idx = tid + i * 256;
            int k   = idx >> 4;
            int d4  = (idx & 15) * 4;
            *(float4*)(Vs + k * 64 + d4) =
                *(const float4*)(vg + (size_t)(kt + k) * HDIM + d4);
        }
        __syncthreads();

        // S = Q . K^T : s[qi][kj], reduction over d
        float s[4][4];
#pragma unroll
        for (int i = 0; i < 4; i++)
#pragma unroll
            for (int j = 0; j < 4; j++) s[i][j] = 0.f;

#pragma unroll 16
        for (int kk = 0; kk < 64; kk++) {
            float4 qf = *(const float4*)(Qt + kk * 68 + ty * 4);
            float4 kf = *(const float4*)(Kt + kk * 68 + tx * 4);
            float qa[4] = {qf.x, qf.y, qf.z, qf.w};
            float ka[4] = {kf.x, kf.y, kf.z, kf.w};
#pragma unroll
            for (int qi = 0; qi < 4; qi++)
#pragma unroll
                for (int kj = 0; kj < 4; kj++)
                    s[qi][kj] += qa[qi] * ka[kj];
        }

        // scale + mask + online softmax (row stats live in registers,
        // replicated across the 16 tx-threads of each row via shfl).
#pragma unroll
        for (int qi = 0; qi < 4; qi++) {
            const float* mrow = mask + ((size_t)b * SEQ + (q0 + ty * 4 + qi)) * SEQ
                                     + kt + tx * 4;
            float4 mk = *(const float4*)mrow;
            s[qi][0] = s[qi][0] * scale + mk.x;
            s[qi][1] = s[qi][1] * scale + mk.y;
            s[qi][2] = s[qi][2] * scale + mk.z;
            s[qi][3] = s[qi][3] * scale + mk.w;

            float mx = fmaxf(fmaxf(s[qi][0], s[qi][1]), fmaxf(s[qi][2], s[qi][3]));
#pragma unroll
            for (int off = 8; off > 0; off >>= 1)
                mx = fmaxf(mx, __shfl_xor_sync(0xffffffffu, mx, off));

            float mnew  = fmaxf(m_r[qi], mx);
            float alpha = __expf(m_r[qi] - mnew);
            float rs = 0.f;
#pragma unroll
            for (int kj = 0; kj < 4; kj++) {
                s[qi][kj] = __expf(s[qi][kj] - mnew);
                rs += s[qi][kj];
            }
#pragma unroll
            for (int off = 8; off > 0; off >>= 1)
                rs += __shfl_xor_sync(0xffffffffu, rs, off);

            l_r[qi] = l_r[qi] * alpha + rs;
            m_r[qi] = mnew;
#pragma unroll
            for (int dj = 0; dj < 4; dj++) o[qi][dj] *= alpha;

            // Write P transposed: Pt[k][q]
#pragma unroll
            for (int kj = 0; kj < 4; kj++)
                Pt[(tx * 4 + kj) * 68 + ty * 4 + qi] = s[qi][kj];
        }
        __syncthreads();

        // O += P . V : reduction over k
#pragma unroll 16
        for (int kk = 0; kk < 64; kk++) {
            float4 pf = *(const float4*)(Pt + kk * 68 + ty * 4);
            float4 vf = *(const float4*)(Vs + kk * 64 + tx * 4);
            float pa[4] = {pf.x, pf.y, pf.z, pf.w};
            float va[4] = {vf.x, vf.y, vf.z, vf.w};
#pragma unroll
            for (int qi = 0; qi < 4; qi++)
#pragma unroll
                for (int dj = 0; dj < 4; dj++)
                    o[qi][dj] += pa[qi] * va[dj];
        }
    }

    // Epilogue: out[s][b][h*64 + d] = o / l
#pragma unroll
    for (int qi = 0; qi < 4; qi++) {
        float inv = 1.0f / l_r[qi];
        int q = q0 + ty * 4 + qi;
        float4 r = make_float4(o[qi][0] * inv, o[qi][1] * inv,
                               o[qi][2] * inv, o[qi][3] * inv);
        *(float4*)(out + ((size_t)q * BATCH + b) * HIDDEN + h * 64 + tx * 4) = r;
    }
}

// ---------------------------------------------------------------------------
extern "C" void kernel_launch(void* const* d_in, const int* in_sizes, int n_in,
                              void* d_out, int out_size)
{
    const float* hs   = (const float*)d_in[0];
    const float* mask = (const float*)d_in[1];
    const float* Wq   = (const float*)d_in[2];
    const float* bq   = (const float*)d_in[3];
    const float* Wk   = (const float*)d_in[4];
    const float* bk   = (const float*)d_in[5];
    const float* Wv   = (const float*)d_in[6];
    const float* bv   = (const float*)d_in[7];
    float* out = (float*)d_out;

    // Idempotent; first call happens outside graph capture (correctness run),
    // so the attribute is already set by the time capture occurs.
    cudaFuncSetAttribute(attn_kernel,
                         cudaFuncAttributeMaxDynamicSharedMemorySize, ATTN_SMEM);

    dim3 g1(HIDDEN / 128, TOK / 128, 3);
    qkv_kernel<<<g1, 256>>>(hs, Wq, bq, Wk, bk, Wv, bv);

    dim3 g2(NH, SEQ / 64);
    attn_kernel<<<g2, 256, ATTN_SMEM>>>(mask, out);
}

// round 3
// speedup vs baseline: 2.7745x; 2.7745x over previous
#include <cuda_runtime.h>
#include <cstdint>

#define SEQ     2048
#define BATCH   2
#define HIDDEN  1024
#define NHEAD   16
#define HDIM    64
#define NH      32
#define TOK     4096

// Scratch (device globals; no runtime allocation). All values tf32-rounded.
__device__ float g_q[(size_t)NH * SEQ * HDIM];   // [n][s][d]
__device__ float g_k[(size_t)NH * HDIM * SEQ];   // [n][d][s]
__device__ float g_v[(size_t)NH * SEQ * HDIM];   // [n][s][d]

// ---------------------------------------------------------------- helpers
__device__ __forceinline__ float tf32f(float x) {
    uint32_t r; asm("cvt.rna.tf32.f32 %0, %1;" : "=r"(r) : "f"(x));
    return __uint_as_float(r);
}
__device__ __forceinline__ float ex2f(float x) {
    float y; asm("ex2.approx.ftz.f32 %0, %1;" : "=f"(y) : "f"(x));
    return y;
}
// m16n8k8 tf32 MMA, D += A*B. A row-major frag (4 regs), B col-major frag (2 regs).
__device__ __forceinline__ void mma8(float d[4], const uint32_t a[4], const uint32_t b[2]) {
    asm volatile(
        "mma.sync.aligned.m16n8k8.row.col.f32.tf32.tf32.f32 "
        "{%0,%1,%2,%3}, {%4,%5,%6,%7}, {%8,%9}, {%0,%1,%2,%3};"
        : "+f"(d[0]), "+f"(d[1]), "+f"(d[2]), "+f"(d[3])
        : "r"(a[0]), "r"(a[1]), "r"(a[2]), "r"(a[3]), "r"(b[0]), "r"(b[1]));
}

// ---------------------------------------------------------------- QKV GEMM
// C[t][c] = sum_k hs[t][k]*W[k][c] + bias[c].  CTA tile 128x128, BK=32.
// 8 warps as 4(M) x 2(N); warp tile 32x64.
// Smem strides chosen for conflict-free fragment reads:
//   A operand needs stride == 4 (mod 32)  -> As[128][36]
//   B operand needs stride == 8 (mod 32)  -> Bs[32][136]
__global__ __launch_bounds__(256, 2) void qkv_kernel(
    const float* __restrict__ hs,
    const float* __restrict__ Wq, const float* __restrict__ bq,
    const float* __restrict__ Wk, const float* __restrict__ bk,
    const float* __restrict__ Wv, const float* __restrict__ bv)
{
    __shared__ float As[128 * 36];
    __shared__ float Bs[32 * 136];

    const int z = blockIdx.z;
    const float* W    = (z == 0) ? Wq : (z == 1) ? Wk : Wv;
    const float* bias = (z == 0) ? bq : (z == 1) ? bk : bv;

    const int tid = threadIdx.x;
    const int lane = tid & 31, wid = tid >> 5;
    const int wm = wid >> 1, wn = wid & 1;
    const int c0 = blockIdx.x * 128;
    const int t0 = blockIdx.y * 128;

    float acc[2][8][4];
#pragma unroll
    for (int i = 0; i < 2; i++)
#pragma unroll
        for (int j = 0; j < 8; j++)
#pragma unroll
            for (int k = 0; k < 4; k++) acc[i][j][k] = 0.f;

    const int r = lane >> 2, cq = lane & 3;

    for (int k0 = 0; k0 < HIDDEN; k0 += 32) {
#pragma unroll
        for (int i = 0; i < 4; i++) {
            int idx = tid + i * 256;
            // A tile 128x32 (round to tf32)
            int ra = idx >> 3, ja = (idx & 7) * 4;
            float4 a = *(const float4*)(hs + (size_t)(t0 + ra) * HIDDEN + k0 + ja);
            *(float4*)(As + ra * 36 + ja) =
                make_float4(tf32f(a.x), tf32f(a.y), tf32f(a.z), tf32f(a.w));
            // B tile 32x128 (round to tf32)
            int rb = idx >> 5, jb = (idx & 31) * 4;
            float4 b = *(const float4*)(W + (size_t)(k0 + rb) * HIDDEN + c0 + jb);
            *(float4*)(Bs + rb * 136 + jb) =
                make_float4(tf32f(b.x), tf32f(b.y), tf32f(b.z), tf32f(b.w));
        }
        __syncthreads();

#pragma unroll
        for (int ks = 0; ks < 4; ks++) {
            const int kk = ks * 8;
            uint32_t af[2][4], bf[8][2];
#pragma unroll
            for (int mf = 0; mf < 2; mf++) {
                int m = wm * 32 + mf * 16 + r;
                af[mf][0] = __float_as_uint(As[m * 36 + kk + cq]);
                af[mf][1] = __float_as_uint(As[(m + 8) * 36 + kk + cq]);
                af[mf][2] = __float_as_uint(As[m * 36 + kk + cq + 4]);
                af[mf][3] = __float_as_uint(As[(m + 8) * 36 + kk + cq + 4]);
            }
#pragma unroll
            for (int nf = 0; nf < 8; nf++) {
                int nn = wn * 64 + nf * 8 + r;
                bf[nf][0] = __float_as_uint(Bs[(kk + cq) * 136 + nn]);
                bf[nf][1] = __float_as_uint(Bs[(kk + cq + 4) * 136 + nn]);
            }
#pragma unroll
            for (int mf = 0; mf < 2; mf++)
#pragma unroll
                for (int nf = 0; nf < 8; nf++)
                    mma8(acc[mf][nf], af[mf], bf[nf]);
        }
        __syncthreads();
    }

    // Epilogue: bias + tf32 round, scatter into head layouts.
    const int c2 = (lane & 3) * 2;
#pragma unroll
    for (int mf = 0; mf < 2; mf++) {
#pragma unroll
        for (int hf = 0; hf < 2; hf++) {
            int t = t0 + wm * 32 + mf * 16 + hf * 8 + r;
            int s = t >> 1, bb = t & 1;
#pragma unroll
            for (int nf = 0; nf < 8; nf++) {
                int cc = c0 + wn * 64 + nf * 8 + c2;
                int h = cc >> 6, d = cc & 63;
                int nH = bb * NHEAD + h;
                float v0 = tf32f(acc[mf][nf][hf * 2 + 0] + bias[cc]);
                float v1 = tf32f(acc[mf][nf][hf * 2 + 1] + bias[cc + 1]);
                if (z == 1) {
                    g_k[((size_t)nH * HDIM + d) * SEQ + s]     = v0;
                    g_k[((size_t)nH * HDIM + d + 1) * SEQ + s] = v1;
                } else {
                    float* dst = (z == 0) ? g_q : g_v;
                    *(float2*)(dst + ((size_t)nH * SEQ + s) * HDIM + d) =
                        make_float2(v0, v1);
                }
            }
        }
    }
}

// ---------------------------------------------------------------- attention
// CTA = (q-tile of 64, head-instance n). 8 warps: mma1 as 2(M)x4(N) over
// S[64][128]; mma2 as 2(M)x4(N) over O[64][64]. Max-free softmax.
// Smem: Qs[64][68], KP = union(Ks[64][136], Ps[64][132]), Vs[128][72], lred[4][64]
#define SM_Q   0
#define SM_KP  (64 * 68)
#define SM_V   (SM_KP + 64 * 136)
#define SM_L   (SM_V + 128 * 72)
#define ATTN_SMEM ((SM_L + 256) * 4)

__global__ __launch_bounds__(256, 2) void attn_kernel(
    const float* __restrict__ mask, float* __restrict__ out)
{
    extern __shared__ float sm[];
    float* Qs = sm + SM_Q;
    float* KP = sm + SM_KP;
    float* Vs = sm + SM_V;
    float* lred = sm + SM_L;

    const int q0 = blockIdx.x * 64;
    const int n  = blockIdx.y;
    const int b = n >> 4, h = n & 15;
    const int tid = threadIdx.x;
    const int lane = tid & 31, wid = tid >> 5;
    const int wm = wid >> 2, wn = wid & 3;
    const int r = lane >> 2, cq = lane & 3, c2 = cq * 2;

    const float* qg = g_q + (size_t)n * SEQ * HDIM;
    const float* kg = g_k + (size_t)n * HDIM * SEQ;
    const float* vg = g_v + (size_t)n * SEQ * HDIM;
    const float* mb = mask + (size_t)b * SEQ * SEQ;

    // Q tile (persistent): Qs[q][d]
#pragma unroll
    for (int i = 0; i < 4; i++) {
        int idx = tid + i * 256;
        int rr = idx >> 4, j = (idx & 15) * 4;
        *(float4*)(Qs + rr * 68 + j) =
            *(const float4*)(qg + ((size_t)q0 + rr) * HDIM + j);
    }

    float o[2][2][4];
    float l[2][2];
#pragma unroll
    for (int i = 0; i < 2; i++)
#pragma unroll
        for (int j = 0; j < 2; j++) {
            l[i][j] = 0.f;
#pragma unroll
            for (int k = 0; k < 4; k++) o[i][j][k] = 0.f;
        }

    const float C1 = 0.18033688011112042f;   // log2(e)/8
    const float C2 = 1.4426950408889634f;    // log2(e)

    for (int kt = 0; kt < SEQ / 128; kt++) {
        __syncthreads();   // previous mma2 done: safe to overwrite KP and Vs
        // K tile: Ks[d][s] from g_k [d][s] rows
#pragma unroll
        for (int i = 0; i < 8; i++) {
            int idx = tid + i * 256;
            int d = idx >> 5, j = (idx & 31) * 4;
            *(float4*)(KP + d * 136 + j) =
                *(const float4*)(kg + (size_t)d * SEQ + kt * 128 + j);
        }
        // V tile: Vs[k][d]
#pragma unroll
        for (int i = 0; i < 8; i++) {
            int idx = tid + i * 256;
            int s = idx >> 4, j = (idx & 15) * 4;
            *(float4*)(Vs + s * 72 + j) =
                *(const float4*)(vg + ((size_t)kt * 128 + s) * HDIM + j);
        }
        __syncthreads();

        // mma1: S[64][128] = Q . K^T  (k-dim = d = 64)
        float s[2][4][4];
#pragma unroll
        for (int i = 0; i < 2; i++)
#pragma unroll
            for (int j = 0; j < 4; j++)
#pragma unroll
                for (int k = 0; k < 4; k++) s[i][j][k] = 0.f;

#pragma unroll
        for (int ks = 0; ks < 8; ks++) {
            const int kk = ks * 8;
            uint32_t af[2][4], bf[4][2];
#pragma unroll
            for (int mf = 0; mf < 2; mf++) {
                int m = wm * 32 + mf * 16 + r;
                af[mf][0] = __float_as_uint(Qs[m * 68 + kk + cq]);
                af[mf][1] = __float_as_uint(Qs[(m + 8) * 68 + kk + cq]);
                af[mf][2] = __float_as_uint(Qs[m * 68 + kk + cq + 4]);
                af[mf][3] = __float_as_uint(Qs[(m + 8) * 68 + kk + cq + 4]);
            }
#pragma unroll
            for (int nf = 0; nf < 4; nf++) {
                int nn = wn * 32 + nf * 8 + r;
                bf[nf][0] = __float_as_uint(KP[(kk + cq) * 136 + nn]);
                bf[nf][1] = __float_as_uint(KP[(kk + cq + 4) * 136 + nn]);
            }
#pragma unroll
            for (int mf = 0; mf < 2; mf++)
#pragma unroll
                for (int nf = 0; nf < 4; nf++)
                    mma8(s[mf][nf], af[mf], bf[nf]);
        }
        __syncthreads();   // all warps done reading Ks before Ps overwrites it

        // softmax (max-free): p = exp2(S*C1 + mask*C2); write Ps[q][k] (tf32)
#pragma unroll
        for (int mf = 0; mf < 2; mf++)
#pragma unroll
            for (int hf = 0; hf < 2; hf++) {
                int rowl = wm * 32 + mf * 16 + hf * 8 + r;
                int qgl  = q0 + rowl;
#pragma unroll
                for (int nf = 0; nf < 4; nf++) {
                    int coll = wn * 32 + nf * 8 + c2;
                    float2 mk = *(const float2*)(mb + (size_t)qgl * SEQ
                                                 + kt * 128 + coll);
                    float p0 = ex2f(s[mf][nf][hf * 2 + 0] * C1 + mk.x * C2);
                    float p1 = ex2f(s[mf][nf][hf * 2 + 1] * C1 + mk.y * C2);
                    l[mf][hf] += p0 + p1;
                    *(float2*)(KP + rowl * 132 + coll) =
                        make_float2(tf32f(p0), tf32f(p1));
                }
            }
        __syncthreads();

        // mma2: O += P . V  (k-dim = 128; warp covers d-range 16, nf<2)
#pragma unroll
        for (int kk8 = 0; kk8 < 16; kk8++) {
            const int kk = kk8 * 8;
            uint32_t af[2][4], bf[2][2];
#pragma unroll
            for (int mf = 0; mf < 2; mf++) {
                int m = wm * 32 + mf * 16 + r;
                af[mf][0] = __float_as_uint(KP[m * 132 + kk + cq]);
                af[mf][1] = __float_as_uint(KP[(m + 8) * 132 + kk + cq]);
                af[mf][2] = __float_as_uint(KP[m * 132 + kk + cq + 4]);
                af[mf][3] = __float_as_uint(KP[(m + 8) * 132 + kk + cq + 4]);
            }
#pragma unroll
            for (int nf = 0; nf < 2; nf++) {
                int dd = wn * 16 + nf * 8 + r;
                bf[nf][0] = __float_as_uint(Vs[(kk + cq) * 72 + dd]);
                bf[nf][1] = __float_as_uint(Vs[(kk + cq + 4) * 72 + dd]);
            }
#pragma unroll
            for (int mf = 0; mf < 2; mf++)
#pragma unroll
                for (int nf = 0; nf < 2; nf++)
                    mma8(o[mf][nf], af[mf], bf[nf]);
        }
    }

    // Row-sum reduction: quad shfl, then across the 4 N-warps via smem.
#pragma unroll
    for (int mf = 0; mf < 2; mf++)
#pragma unroll
        for (int hf = 0; hf < 2; hf++) {
            float v = l[mf][hf];
            v += __shfl_xor_sync(0xffffffffu, v, 1);
            v += __shfl_xor_sync(0xffffffffu, v, 2);
            l[mf][hf] = v;
            if (cq == 0)
                lred[wn * 64 + wm * 32 + mf * 16 + hf * 8 + r] = v;
        }
    __syncthreads();

#pragma unroll
    for (int mf = 0; mf < 2; mf++)
#pragma unroll
        for (int hf = 0; hf < 2; hf++) {
            int rowl = wm * 32 + mf * 16 + hf * 8 + r;
            float lt = lred[rowl] + lred[64 + rowl] + lred[128 + rowl] + lred[192 + rowl];
            float inv = 1.0f / lt;
            int qgl = q0 + rowl;
#pragma unroll
            for (int nf = 0; nf < 2; nf++) {
                int dd = wn * 16 + nf * 8 + c2;
                float2 ov = make_float2(o[mf][nf][hf * 2 + 0] * inv,
                                        o[mf][nf][hf * 2 + 1] * inv);
                *(float2*)(out + ((size_t)qgl * BATCH + b) * HIDDEN + h * 64 + dd) = ov;
            }
        }
}

// ----------------------------------------------------------------
extern "C" void kernel_launch(void* const* d_in, const int* in_sizes, int n_in,
                              void* d_out, int out_size)
{
    const float* hs   = (const float*)d_in[0];
    const float* mask = (const float*)d_in[1];
    const float* Wq   = (const float*)d_in[2];
    const float* bq   = (const float*)d_in[3];
    const float* Wk   = (const float*)d_in[4];
    const float* bk   = (const float*)d_in[5];
    const float* Wv   = (const float*)d_in[6];
    const float* bv   = (const float*)d_in[7];
    float* out = (float*)d_out;

    cudaFuncSetAttribute(attn_kernel,
                         cudaFuncAttributeMaxDynamicSharedMemorySize, ATTN_SMEM);

    dim3 g1(HIDDEN / 128, TOK / 128, 3);
    qkv_kernel<<<g1, 256>>>(hs, Wq, bq, Wk, bk, Wv, bv);

    dim3 g2(SEQ / 64, NH);
    attn_kernel<<<g2, 256, ATTN_SMEM>>>(mask, out);
}